// round 15
// baseline (speedup 1.0000x reference)
#include <cuda_runtime.h>
#include <cuda_bf16.h>
#include <cuda_fp16.h>
#include <math.h>
#include <stdint.h>

#define Dm   512
#define Hh   8
#define DK   64
#define DFFm 2048
#define Lm   4
#define Bb   2
#define Sm   1024
#define Vv   50257
#define MR   (Bb*Sm)
#define NQKV (3*Dm)

__device__ float g_x[MR*Dm];
__device__ __half g_h16[MR*Dm];                     // LN out (fp16)
__device__ __half g_qkvh[MR*NQKV], g_qkvl[MR*NQKV]; // QKV out hi/lo (fp16)
__device__ __half g_o16[MR*Dm];                     // attn out (fp16)
__device__ __half g_f16[MR*DFFm];                   // FFN1 out (fp16)

__device__ __half g_wqkv[Lm*NQKV*Dm];
__device__ float  g_bqkv[Lm*NQKV];
__device__ __half g_wo[Lm*Dm*Dm];
__device__ __half g_w1[Lm*DFFm*Dm];
__device__ __half g_w2[Lm*Dm*DFFm];
__device__ __half g_whead[(size_t)Vv*Dm];

__device__ __forceinline__ unsigned saddr(const void* p) {
    return (unsigned)__cvta_generic_to_shared(p);
}
__device__ __forceinline__ void ldsm4(unsigned* d, unsigned a) {
    asm volatile("ldmatrix.sync.aligned.m8n8.x4.shared.b16 {%0,%1,%2,%3}, [%4];"
        : "=r"(d[0]), "=r"(d[1]), "=r"(d[2]), "=r"(d[3]) : "r"(a));
}
__device__ __forceinline__ void ldsm4t(unsigned* d, unsigned a) {
    asm volatile("ldmatrix.sync.aligned.m8n8.x4.trans.shared.b16 {%0,%1,%2,%3}, [%4];"
        : "=r"(d[0]), "=r"(d[1]), "=r"(d[2]), "=r"(d[3]) : "r"(a));
}
__device__ __forceinline__ void mma16816h(float* c, const unsigned* a, const unsigned* b) {
    asm volatile("mma.sync.aligned.m16n8k16.row.col.f32.f16.f16.f32 "
        "{%0,%1,%2,%3}, {%4,%5,%6,%7}, {%8,%9}, {%0,%1,%2,%3};"
        : "+f"(c[0]), "+f"(c[1]), "+f"(c[2]), "+f"(c[3])
        : "r"(a[0]), "r"(a[1]), "r"(a[2]), "r"(a[3]), "r"(b[0]), "r"(b[1]));
}
__device__ __forceinline__ void cp16(uint32_t d, const void* s) {
    asm volatile("cp.async.cg.shared.global [%0], [%1], 16;" :: "r"(d), "l"(s));
}
__device__ __forceinline__ void cp16z(uint32_t d, const void* s, bool ok) {
    int sz = ok ? 16 : 0;
    asm volatile("cp.async.cg.shared.global [%0], [%1], 16, %2;" :: "r"(d), "l"(s), "r"(sz));
}
__device__ __forceinline__ float gelu(float v) {
    return 0.5f * v * (1.0f + erff(v * 0.70710678118654752f));
}
__device__ __forceinline__ unsigned pack2h(float x, float y) {
    __half2 p; p.x = __float2half_rn(x); p.y = __float2half_rn(y);
    return *reinterpret_cast<unsigned*>(&p);
}
__device__ __forceinline__ void packsplit2h(float x, float y, unsigned& hi, unsigned& lo) {
    __half hx = __float2half_rn(x), hy = __float2half_rn(y);
    __half lx = __float2half_rn(x - __half2float(hx));
    __half ly = __float2half_rn(y - __half2float(hy));
    __half2 H; H.x = hx; H.y = hy;
    __half2 L; L.x = lx; L.y = ly;
    hi = *reinterpret_cast<unsigned*>(&H);
    lo = *reinterpret_cast<unsigned*>(&L);
}
__device__ __forceinline__ void store_h4(__half* d, float4 v) {
    __half2 a, b;
    a.x = __float2half_rn(v.x); a.y = __float2half_rn(v.y);
    b.x = __float2half_rn(v.z); b.y = __float2half_rn(v.w);
    reinterpret_cast<__half2*>(d)[0] = a;
    reinterpret_cast<__half2*>(d)[1] = b;
}

// fused split of all layer weights + packed QKV bias (all -> fp16 single)
#define WA4    (Dm*Dm/4)
#define QKVTOT (3*Lm*WA4)
#define WOTOT  (Lm*WA4)
#define FTOT   (Lm*DFFm*Dm/4)
#define BIAS4  (Lm*NQKV/4)
#define TOT4   (QKVTOT + WOTOT + 2*FTOT + BIAS4)
__global__ void split_layers_kernel(const float* __restrict__ Wq, const float* __restrict__ Wk,
                                    const float* __restrict__ Wv, const float* __restrict__ Wo,
                                    const float* __restrict__ W1, const float* __restrict__ W2,
                                    const float* __restrict__ bq, const float* __restrict__ bk,
                                    const float* __restrict__ bv) {
    int idx = blockIdx.x * blockDim.x + threadIdx.x;
    if (idx >= TOT4) return;
    if (idx < QKVTOT) {
        int sect = idx / (Lm*WA4);
        int rem  = idx % (Lm*WA4);
        int l = rem / WA4, e = rem % WA4;
        int r = e / (Dm/4), c4 = e % (Dm/4);
        const float* src = sect == 0 ? Wq : (sect == 1 ? Wk : Wv);
        float4 v = reinterpret_cast<const float4*>(src)[(size_t)l*WA4 + e];
        size_t d4 = ((size_t)l*NQKV + sect*Dm + r)*(Dm/4) + c4;
        store_h4(g_wqkv + d4*4, v);
    } else if (idx < QKVTOT + WOTOT) {
        int e = idx - QKVTOT;
        store_h4(g_wo + (size_t)e*4, reinterpret_cast<const float4*>(Wo)[e]);
    } else if (idx < QKVTOT + WOTOT + FTOT) {
        int e = idx - QKVTOT - WOTOT;
        store_h4(g_w1 + (size_t)e*4, reinterpret_cast<const float4*>(W1)[e]);
    } else if (idx < QKVTOT + WOTOT + 2*FTOT) {
        int e = idx - QKVTOT - WOTOT - FTOT;
        store_h4(g_w2 + (size_t)e*4, reinterpret_cast<const float4*>(W2)[e]);
    } else {
        int e = idx - QKVTOT - WOTOT - 2*FTOT;
        #pragma unroll
        for (int j = 0; j < 4; j++) {
            int i = e*4 + j;
            int l = i / NQKV, c = i % NQKV;
            g_bqkv[i] = (c < Dm) ? bq[l*Dm + c]
                       : (c < 2*Dm ? bk[l*Dm + c - Dm] : bv[l*Dm + c - 2*Dm]);
        }
    }
}

__global__ void split_head_kernel(const float* __restrict__ W) {
    size_t idx = (size_t)blockIdx.x * blockDim.x + threadIdx.x;
    size_t n4 = (size_t)Vv*Dm/4;
    if (idx >= n4) return;
    store_h4(g_whead + idx*4, reinterpret_cast<const float4*>(W)[idx]);
}

__global__ void embed_kernel(const int* __restrict__ tok, const float* __restrict__ emb,
                             const float* __restrict__ pos, float* __restrict__ x) {
    int idx = blockIdx.x * blockDim.x + threadIdx.x;
    if (idx >= MR*Dm) return;
    int row = idx / Dm, d = idx % Dm;
    x[idx] = emb[tok[row]*Dm + d] + pos[(row % Sm)*Dm + d];
}

// LN -> fp16 (single)
__global__ void __launch_bounds__(128) ln_kernel(const float* __restrict__ x,
                                                 const float* __restrict__ g,
                                                 const float* __restrict__ b,
                                                 __half* __restrict__ o16) {
    int row = blockIdx.x, t = threadIdx.x;
    const float4 v4 = reinterpret_cast<const float4*>(x + (size_t)row*Dm)[t];
    __shared__ float red[4];
    float s = v4.x + v4.y + v4.z + v4.w;
    #pragma unroll
    for (int o = 16; o > 0; o >>= 1) s += __shfl_xor_sync(0xffffffffu, s, o);
    if ((t & 31) == 0) red[t >> 5] = s;
    __syncthreads();
    float mean = (red[0]+red[1]+red[2]+red[3]) * (1.0f/Dm);
    __syncthreads();
    float dx = v4.x-mean, dy = v4.y-mean, dz = v4.z-mean, dw = v4.w-mean;
    float ss = dx*dx + dy*dy + dz*dz + dw*dw;
    #pragma unroll
    for (int o = 16; o > 0; o >>= 1) ss += __shfl_xor_sync(0xffffffffu, ss, o);
    if ((t & 31) == 0) red[t >> 5] = ss;
    __syncthreads();
    float inv = rsqrtf((red[0]+red[1]+red[2]+red[3])*(1.0f/Dm) + 1e-5f);
    float4 gg = reinterpret_cast<const float4*>(g)[t];
    float4 bb = reinterpret_cast<const float4*>(b)[t];
    float o0 = dx*inv*gg.x + bb.x, o1 = dy*inv*gg.y + bb.y;
    float o2 = dz*inv*gg.z + bb.z, o3 = dw*inv*gg.w + bb.w;
    size_t off = (size_t)row*Dm + 4*t;
    *reinterpret_cast<unsigned*>(o16+off)   = pack2h(o0, o1);
    *reinterpret_cast<unsigned*>(o16+off+2) = pack2h(o2, o3);
}

// pipelined fp16 1-MMA HMMA GEMM (A single fp16, W single fp16).
// Warp grid: 4 (m) x TH/128 (n). Warp tile: (BM/4) x (BN/(TH/128)).
// OUTMODE: 0 fp32; 1 fp32+residual; 3 fp16 hi/lo out; 4 fp16 single out.
template<int BM, int BN, int ACT, int OUTMODE, int TH, int MINB>
__global__ void __launch_bounds__(TH, MINB)
pgemm(const __half* __restrict__ A, const __half* __restrict__ W,
      const float* __restrict__ bias, const float* __restrict__ Rsd,
      float* __restrict__ C, __half* __restrict__ Ch, __half* __restrict__ Cl,
      int Nn, int Kn) {
    constexpr int BK = 32;
    constexpr int WARPS_N = TH/128;
    constexpr int WN = BN/WARPS_N;
    constexpr int NB = WN/16;
    constexpr int MI = BM/64;              // m-frags (16-row) per warp
    constexpr int AST = BM*40, WST = BN*40;
    constexpr int OFF_W = AST*2;
    constexpr int STAGE_B = (AST + WST)*2;

    extern __shared__ __align__(16) char smem[];
    uint32_t sb = saddr(smem);
    int tid = threadIdx.x, lane = tid & 31, warp = tid >> 5;
    int m0 = (warp & 3)*(BM/4), n0 = (warp >> 2)*WN;

    int gx = gridDim.x, gy = gridDim.y;
    int bid = blockIdx.y * gx + blockIdx.x;
    const int GM = 8;
    int gsz = GM * gx;
    int grp = bid / gsz, rem = bid % gsz;
    int gmr = (gy - grp*GM < GM) ? (gy - grp*GM) : GM;
    int bm = (grp*GM + rem % gmr) * BM;
    int bn = (rem / gmr) * BN;
    int nK = Kn / BK;

    float acc[MI][2*NB][4];
    #pragma unroll
    for (int i = 0; i < MI; i++)
        #pragma unroll
        for (int j = 0; j < 2*NB; j++)
            #pragma unroll
            for (int r = 0; r < 4; r++) acc[i][j][r] = 0.f;

    auto load_stage = [&](int s, int kt) {
        uint32_t base = sb + s*STAGE_B;
        int k0 = kt*BK;
        #pragma unroll
        for (int i = tid; i < BM*4; i += TH) {
            int r = i >> 2, c = (i & 3) << 3;
            cp16(base + (r*40 + c)*2, A + (size_t)(bm + r)*Kn + k0 + c);
        }
        #pragma unroll
        for (int i = tid; i < BN*4; i += TH) {
            int r = i >> 2, c = (i & 3) << 3;
            int gn = bn + r;
            cp16z(base + OFF_W + (r*40 + c)*2, W + (size_t)gn*Kn + k0 + c, gn < Nn);
        }
        asm volatile("cp.async.commit_group;" ::: "memory");
    };

    load_stage(0, 0);
    load_stage(1, 1);

    for (int kt = 0; kt < nK; kt++) {
        if (kt == nK - 1) asm volatile("cp.async.wait_group 0;" ::: "memory");
        else              asm volatile("cp.async.wait_group 1;" ::: "memory");
        __syncthreads();
        if (kt + 2 < nK) load_stage((kt + 2) % 3, kt + 2);

        uint32_t base = sb + (kt % 3)*STAGE_B;
        #pragma unroll
        for (int ks = 0; ks < 2; ks++) {
            unsigned ah[MI][4], bh[NB][4];
            int ca = ks*16 + ((lane >> 4) << 3);
            #pragma unroll
            for (int i = 0; i < MI; i++) {
                int rw = m0 + i*16 + (lane & 15);
                ldsm4(ah[i], base + (rw*40 + ca)*2);
            }
            int cb = ks*16 + (((lane >> 3) & 1) << 3);
            #pragma unroll
            for (int j = 0; j < NB; j++) {
                int rw = n0 + j*16 + ((lane >> 4) << 3) + (lane & 7);
                ldsm4(bh[j], base + OFF_W + (rw*40 + cb)*2);
            }
            #pragma unroll
            for (int i = 0; i < MI; i++)
                #pragma unroll
                for (int jj = 0; jj < 2*NB; jj++)
                    mma16816h(acc[i][jj], ah[i], &bh[jj >> 1][(jj & 1)*2]);
        }
    }

    bool vecok = ((Nn & 1) == 0) && (bn + BN <= Nn);
    #pragma unroll
    for (int i = 0; i < MI; i++) {
        #pragma unroll
        for (int jj = 0; jj < 2*NB; jj++) {
            int r0 = bm + m0 + i*16 + (lane >> 2);
            int cc = bn + n0 + (jj >> 1)*16 + (jj & 1)*8 + ((lane & 3) << 1);
            #pragma unroll
            for (int hr = 0; hr < 2; hr++) {
                int r = r0 + hr*8;
                float v0 = acc[i][jj][hr*2+0], v1 = acc[i][jj][hr*2+1];
                if (OUTMODE == 3) {
                    v0 += bias[cc]; v1 += bias[cc+1];
                    if (ACT) { v0 = gelu(v0); v1 = gelu(v1); }
                    unsigned ph, pl;
                    packsplit2h(v0, v1, ph, pl);
                    *reinterpret_cast<unsigned*>(Ch + (size_t)r*Nn + cc) = ph;
                    *reinterpret_cast<unsigned*>(Cl + (size_t)r*Nn + cc) = pl;
                } else if (OUTMODE == 4) {
                    v0 += bias[cc]; v1 += bias[cc+1];
                    if (ACT) { v0 = gelu(v0); v1 = gelu(v1); }
                    *reinterpret_cast<unsigned*>(Ch + (size_t)r*Nn + cc) = pack2h(v0, v1);
                } else if (vecok) {
                    float2 v;
                    v.x = v0 + bias[cc]; v.y = v1 + bias[cc+1];
                    if (ACT) { v.x = gelu(v.x); v.y = gelu(v.y); }
                    if (OUTMODE == 1) {
                        float2 r2 = *reinterpret_cast<const float2*>(Rsd + (size_t)r*Nn + cc);
                        v.x += r2.x; v.y += r2.y;
                    }
                    *reinterpret_cast<float2*>(C + (size_t)r*Nn + cc) = v;
                } else {
                    if (cc < Nn) {
                        float v = v0 + bias[cc];
                        if (ACT) v = gelu(v);
                        if (OUTMODE == 1) v += Rsd[(size_t)r*Nn + cc];
                        C[(size_t)r*Nn + cc] = v;
                    }
                    if (cc + 1 < Nn) {
                        float v = v1 + bias[cc+1];
                        if (ACT) v = gelu(v);
                        if (OUTMODE == 1) v += Rsd[(size_t)r*Nn + cc + 1];
                        C[(size_t)r*Nn + cc + 1] = v;
                    }
                }
            }
        }
    }
}

// tensor-core flash attention (fp16): Q exact hi/lo, K/V hi only; output fp16 single.
#define AT_SMEM 55296
__global__ void __launch_bounds__(128)
attn_kernel(const __half* __restrict__ qkvh, const __half* __restrict__ qkvl,
            __half* __restrict__ o16) {
    extern __shared__ __align__(16) char sm[];
    uint32_t sb = saddr(sm);
    int qt = blockIdx.x, bh = blockIdx.y;
    int b = bh >> 3, h = bh & 7;
    int tid = threadIdx.x, lane = tid & 31, w = tid >> 5;
    int tokbase = b * Sm;
    const int QL_B = 9216, ST0 = 18432, ST_SZ = 18432;

    #pragma unroll
    for (int t = 0; t < 4; t++) {
        int i = tid + t*128;
        int r = i >> 3, c8 = i & 7;
        uint32_t off = r*144 + c8*16;
        size_t g = (size_t)(tokbase + qt*64 + r)*NQKV + h*DK + c8*8;
        cp16(sb + off,        qkvh + g);
        cp16(sb + QL_B + off, qkvl + g);
    }
    {
        uint32_t base = sb + ST0;
        #pragma unroll
        for (int t = 0; t < 4; t++) {
            int i = tid + t*128;
            int r = i >> 3, c8 = i & 7;
            uint32_t off = r*144 + c8*16;
            size_t g = (size_t)(tokbase + r)*NQKV + h*DK + c8*8;
            cp16(base + off,        qkvh + g + Dm);
            cp16(base + 9216 + off, qkvh + g + 2*Dm);
        }
    }
    asm volatile("cp.async.commit_group;" ::: "memory");

    unsigned qfh[4][4], qfl[4][4];
    float ao[8][4];
    #pragma unroll
    for (int d = 0; d < 8; d++)
        #pragma unroll
        for (int t = 0; t < 4; t++) ao[d][t] = 0.f;
    float m0 = -1e30f, m1 = -1e30f, l0 = 0.f, l1 = 0.f;

    for (int kt = 0; kt <= qt; kt++) {
        asm volatile("cp.async.wait_group 0;" ::: "memory");
        __syncthreads();
        if (kt == 0) {
            #pragma unroll
            for (int ks = 0; ks < 4; ks++) {
                uint32_t a = sb + (w*16 + (lane & 15))*144 + (ks*16 + ((lane >> 4) << 3))*2;
                ldsm4(qfh[ks], a);
                ldsm4(qfl[ks], a + QL_B);
            }
        }
        if (kt < qt) {
            uint32_t base = sb + ST0 + ((kt+1) & 1)*ST_SZ;
            #pragma unroll
            for (int t = 0; t < 4; t++) {
                int i = tid + t*128;
                int r = i >> 3, c8 = i & 7;
                uint32_t off = r*144 + c8*16;
                size_t g = (size_t)(tokbase + (kt+1)*64 + r)*NQKV + h*DK + c8*8;
                cp16(base + off,        qkvh + g + Dm);
                cp16(base + 9216 + off, qkvh + g + 2*Dm);
            }
            asm volatile("cp.async.commit_group;" ::: "memory");
        }
        uint32_t kb = sb + ST0 + (kt & 1)*ST_SZ;

        float sc[8][4];
        #pragma unroll
        for (int j = 0; j < 8; j++)
            #pragma unroll
            for (int t = 0; t < 4; t++) sc[j][t] = 0.f;

        #pragma unroll
        for (int ks = 0; ks < 4; ks++) {
            unsigned kh[4][4];
            #pragma unroll
            for (int jp = 0; jp < 4; jp++) {
                uint32_t a = kb + (jp*16 + ((lane >> 4) << 3) + (lane & 7))*144
                           + (ks*16 + (((lane >> 3) & 1) << 3))*2;
                ldsm4(kh[jp], a);
            }
            #pragma unroll
            for (int jp = 0; jp < 4; jp++)
                #pragma unroll
                for (int sub = 0; sub < 2; sub++) {
                    int j = jp*2 + sub;
                    mma16816h(sc[j], qfh[ks], &kh[jp][sub*2]);
                    mma16816h(sc[j], qfl[ks], &kh[jp][sub*2]);
                }
        }

        int rg = qt*64 + w*16 + (lane >> 2);
        #pragma unroll
        for (int j = 0; j < 8; j++)
            #pragma unroll
            for (int t = 0; t < 4; t++) sc[j][t] *= 0.125f;
        if (kt == qt) {
            #pragma unroll
            for (int j = 0; j < 8; j++) {
                int cg = kt*64 + j*8 + ((lane & 3) << 1);
                if (cg     > rg)     sc[j][0] = -1e30f;
                if (cg + 1 > rg)     sc[j][1] = -1e30f;
                if (cg     > rg + 8) sc[j][2] = -1e30f;
                if (cg + 1 > rg + 8) sc[j][3] = -1e30f;
            }
        }

        float mx0 = -1e30f, mx1 = -1e30f;
        #pragma unroll
        for (int j = 0; j < 8; j++) {
            mx0 = fmaxf(mx0, fmaxf(sc[j][0], sc[j][1]));
            mx1 = fmaxf(mx1, fmaxf(sc[j][2], sc[j][3]));
        }
        mx0 = fmaxf(mx0, __shfl_xor_sync(0xffffffffu, mx0, 1));
        mx0 = fmaxf(mx0, __shfl_xor_sync(0xffffffffu, mx0, 2));
        mx1 = fmaxf(mx1, __shfl_xor_sync(0xffffffffu, mx1, 1));
        mx1 = fmaxf(mx1, __shfl_xor_sync(0xffffffffu, mx1, 2));
        float nm0 = fmaxf(m0, mx0), nm1 = fmaxf(m1, mx1);
        float c0 = __expf(m0 - nm0), c1 = __expf(m1 - nm1);
        m0 = nm0; m1 = nm1;
        float s0 = 0.f, s1 = 0.f;
        #pragma unroll
        for (int j = 0; j < 8; j++) {
            sc[j][0] = __expf(sc[j][0] - m0);
            sc[j][1] = __expf(sc[j][1] - m0);
            sc[j][2] = __expf(sc[j][2] - m1);
            sc[j][3] = __expf(sc[j][3] - m1);
            s0 += sc[j][0] + sc[j][1];
            s1 += sc[j][2] + sc[j][3];
        }
        l0 = l0*c0 + s0;
        l1 = l1*c1 + s1;
        #pragma unroll
        for (int d = 0; d < 8; d++) {
            ao[d][0] *= c0; ao[d][1] *= c0;
            ao[d][2] *= c1; ao[d][3] *= c1;
        }

        unsigned ph[4][4], pl[4][4];
        #pragma unroll
        for (int kp = 0; kp < 4; kp++) {
            int j0 = 2*kp, j1 = 2*kp + 1;
            packsplit2h(sc[j0][0], sc[j0][1], ph[kp][0], pl[kp][0]);
            packsplit2h(sc[j0][2], sc[j0][3], ph[kp][1], pl[kp][1]);
            packsplit2h(sc[j1][0], sc[j1][1], ph[kp][2], pl[kp][2]);
            packsplit2h(sc[j1][2], sc[j1][3], ph[kp][3], pl[kp][3]);
        }

        #pragma unroll
        for (int kp = 0; kp < 4; kp++) {
            unsigned vh[4][4];
            #pragma unroll
            for (int dp = 0; dp < 4; dp++) {
                uint32_t a = kb + 9216 + (kp*16 + (((lane >> 3) & 1) << 3) + (lane & 7))*144
                           + (dp*16 + ((lane >> 4) << 3))*2;
                ldsm4t(vh[dp], a);
            }
            #pragma unroll
            for (int dp = 0; dp < 4; dp++)
                #pragma unroll
                for (int sub = 0; sub < 2; sub++) {
                    int d = dp*2 + sub;
                    mma16816h(ao[d], ph[kp], &vh[dp][sub*2]);
                    mma16816h(ao[d], pl[kp], &vh[dp][sub*2]);
                }
        }
    }

    l0 += __shfl_xor_sync(0xffffffffu, l0, 1);
    l0 += __shfl_xor_sync(0xffffffffu, l0, 2);
    l1 += __shfl_xor_sync(0xffffffffu, l1, 1);
    l1 += __shfl_xor_sync(0xffffffffu, l1, 2);
    float i0 = 1.f / l0, i1 = 1.f / l1;
    int row0 = tokbase + qt*64 + w*16 + (lane >> 2);
    #pragma unroll
    for (int d = 0; d < 8; d++) {
        int col = h*DK + d*8 + ((lane & 3) << 1);
        *reinterpret_cast<unsigned*>(o16 + (size_t)row0*Dm + col)     = pack2h(ao[d][0]*i0, ao[d][1]*i0);
        *reinterpret_cast<unsigned*>(o16 + (size_t)(row0+8)*Dm + col) = pack2h(ao[d][2]*i1, ao[d][3]*i1);
    }
}

extern "C" void kernel_launch(void* const* d_in, const int* in_sizes, int n_in,
                              void* d_out, int out_size) {
    const int*   tokens = (const int*)  d_in[0];
    const float* emb    = (const float*)d_in[1];
    const float* pos    = (const float*)d_in[2];
    const float* Wq     = (const float*)d_in[3];
    const float* bq     = (const float*)d_in[4];
    const float* Wk     = (const float*)d_in[5];
    const float* bk     = (const float*)d_in[6];
    const float* Wv     = (const float*)d_in[7];
    const float* bv     = (const float*)d_in[8];
    const float* Wo     = (const float*)d_in[9];
    const float* bo     = (const float*)d_in[10];
    const float* ln1g   = (const float*)d_in[11];
    const float* ln1b   = (const float*)d_in[12];
    const float* W1     = (const float*)d_in[13];
    const float* b1     = (const float*)d_in[14];
    const float* W2     = (const float*)d_in[15];
    const float* b2     = (const float*)d_in[16];
    const float* ln2g   = (const float*)d_in[17];
    const float* ln2b   = (const float*)d_in[18];
    const float* lnfg   = (const float*)d_in[19];
    const float* lnfb   = (const float*)d_in[20];
    const float* Whead  = (const float*)d_in[21];
    const float* bhead  = (const float*)d_in[22];
    float* out = (float*)d_out;

    float *x, *bqkv;
    __half *h16,*qh,*ql,*o16,*f16;
    __half *wqkv,*wop,*w1p,*w2p,*whead;
    cudaGetSymbolAddress((void**)&x, g_x);
    cudaGetSymbolAddress((void**)&bqkv, g_bqkv);
    cudaGetSymbolAddress((void**)&h16, g_h16);
    cudaGetSymbolAddress((void**)&qh, g_qkvh); cudaGetSymbolAddress((void**)&ql, g_qkvl);
    cudaGetSymbolAddress((void**)&o16, g_o16);
    cudaGetSymbolAddress((void**)&f16, g_f16);
    cudaGetSymbolAddress((void**)&wqkv, g_wqkv);
    cudaGetSymbolAddress((void**)&wop, g_wo);
    cudaGetSymbolAddress((void**)&w1p, g_w1);  cudaGetSymbolAddress((void**)&w2p, g_w2);
    cudaGetSymbolAddress((void**)&whead, g_whead);

    const int SMV = 3 * ((128*40 + 64*40) * 2);    // 46080: BM=128/BN=64, 3 CTA/SM
    const int SMT = 3 * ((256*40 + 64*40) * 2);    // 76800: BM=256/BN=64, 2 CTA/SM
    cudaFuncSetAttribute((const void*)pgemm<128,64,0,3,256,3>, cudaFuncAttributeMaxDynamicSharedMemorySize, SMV);
    cudaFuncSetAttribute((const void*)pgemm<128,64,0,1,256,3>, cudaFuncAttributeMaxDynamicSharedMemorySize, SMV);
    cudaFuncSetAttribute((const void*)pgemm<256,64,1,4,256,2>, cudaFuncAttributeMaxDynamicSharedMemorySize, SMT);
    cudaFuncSetAttribute((const void*)pgemm<256,64,0,0,256,2>, cudaFuncAttributeMaxDynamicSharedMemorySize, SMT);
    cudaFuncSetAttribute((const void*)attn_kernel, cudaFuncAttributeMaxDynamicSharedMemorySize, AT_SMEM);

    const int TS = 256;
    dim3 gQKV(NQKV/64, MR/128);            // 384 CTAs
    dim3 gN512(Dm/64,  MR/128);            // 128 CTAs
    dim3 gFF1(DFFm/64, MR/256);            // (32,8) = 256 CTAs, single wave
    dim3 gHead((Vv + 63)/64, MR/256);      // (786,8) = 6288 CTAs
    dim3 gAttn(Sm/64, Bb*Hh);

    // visible launch #4 = QKV pgemm (ncu capture target)
    split_layers_kernel<<<(TOT4+TS-1)/TS, TS>>>(Wq, Wk, Wv, Wo, W1, W2, bq, bk, bv);
    embed_kernel<<<(MR*Dm + 255)/256, 256>>>(tokens, emb, pos, x);
    ln_kernel<<<MR, 128>>>(x, ln1g, ln1b, h16);
    pgemm<128,64,0,3,256,3><<<gQKV,256,SMV>>>(h16, wqkv, bqkv, nullptr, nullptr, qh, ql, NQKV, Dm);
    split_head_kernel<<<(int)(((size_t)Vv*Dm/4 + TS-1)/TS), TS>>>(Whead);

    for (int l = 0; l < Lm; l++) {
        size_t oQ = (size_t)l*NQKV*Dm, oA = (size_t)l*Dm*Dm;
        size_t oF1 = (size_t)l*DFFm*Dm, oF2 = (size_t)l*Dm*DFFm;

        if (l > 0) {
            ln_kernel<<<MR, 128>>>(x, ln1g + l*Dm, ln1b + l*Dm, h16);
            pgemm<128,64,0,3,256,3><<<gQKV,256,SMV>>>(h16, wqkv+oQ, bqkv+l*NQKV, nullptr, nullptr, qh, ql, NQKV, Dm);
        }
        attn_kernel<<<gAttn, 128, AT_SMEM>>>(qh, ql, o16);
        pgemm<128,64,0,1,256,3><<<gN512,256,SMV>>>(o16, wop+oA, bo+l*Dm, x, x, nullptr, nullptr, Dm, Dm);

        ln_kernel<<<MR, 128>>>(x, ln2g + l*Dm, ln2b + l*Dm, h16);
        pgemm<256,64,1,4,256,2><<<gFF1,256,SMT>>>(h16, w1p+oF1, b1+l*DFFm, nullptr, nullptr, f16, nullptr, DFFm, Dm);
        pgemm<128,64,0,1,256,3><<<gN512,256,SMV>>>(f16, w2p+oF2, b2+l*Dm, x, x, nullptr, nullptr, Dm, DFFm);
    }

    ln_kernel<<<MR, 128>>>(x, lnfg, lnfb, h16);
    pgemm<256,64,0,0,256,2><<<gHead,256,SMT>>>(h16, whead, bhead, nullptr, out, nullptr, nullptr, Vv, Dm);
}